// round 11
// baseline (speedup 1.0000x reference)
#include <cuda_runtime.h>
#include <cuda_bf16.h>
#include <cstdint>

#define CDIM    128
#define NEXP    8
#define SPATIAL 32768
#define NVOX    65536
#define CHUNK   512
#define NCHUNK  (NVOX / CHUNK)   // 128
#define SUBV    128
#define PKB     272           // expert smem tile row pitch (bytes)
#define VP      68            // gate smem [c][v] pitch (floats)
#define CP      65            // combine smem [c][v] pitch (floats)

// ---------------- device scratch ----------------
__device__ __nv_bfloat16 g_xbt[(size_t)NVOX * CDIM];   // x, bf16, [v][c]
__device__ __nv_bfloat16 g_y0h[(size_t)NVOX * CDIM];   // slot-0 y, bf16, [v][c]
__device__ __nv_bfloat16 g_y1h[(size_t)NVOX * CDIM];   // slot-1 y, bf16, [v][c]
__device__ __nv_bfloat16 g_w1b[NEXP * CDIM * CDIM];    // W1 bf16, [e][o][k]
__device__ __nv_bfloat16 g_w2b[NEXP * CDIM * CDIM];    // W2 bf16, [e][o][k]
__device__ unsigned short g_route[NVOX];
__device__ float          g_prob[NVOX];

__device__ __forceinline__ uint32_t smem_u32(const void* p) {
    uint32_t a;
    asm("{ .reg .u64 t; cvta.to.shared.u64 t, %1; cvt.u32.u64 %0, t; }" : "=r"(a) : "l"(p));
    return a;
}

#define LDSM_X4(r0, r1, r2, r3, addr) \
    asm volatile("ldmatrix.sync.aligned.m8n8.x4.shared.b16 {%0,%1,%2,%3}, [%4];" \
        : "=r"(r0), "=r"(r1), "=r"(r2), "=r"(r3) : "r"(addr))

#define MMA16816(c, a, b0v, b1v) \
    asm volatile("mma.sync.aligned.m16n8k16.row.col.f32.bf16.bf16.f32 " \
        "{%0,%1,%2,%3}, {%4,%5,%6,%7}, {%8,%9}, {%0,%1,%2,%3};" \
        : "+f"((c)[0]), "+f"((c)[1]), "+f"((c)[2]), "+f"((c)[3]) \
        : "r"((a)[0]), "r"((a)[1]), "r"((a)[2]), "r"((a)[3]), "r"(b0v), "r"(b1v))

#define CP_ASYNC16(dst, src) \
    asm volatile("cp.async.ca.shared.global [%0], [%1], 16;" :: "r"(dst), "l"(src))
#define CP_COMMIT() asm volatile("cp.async.commit_group;")
#define CP_WAIT0()  asm volatile("cp.async.wait_group 0;" ::: "memory")
#define PREF_L2(p)  asm volatile("prefetch.global.L2 [%0];" :: "l"(p))

// ================= K1: gate + bf16 xT emission + distributed weight conversion =================
__global__ __launch_bounds__(256)
void gate_kernel(const float* __restrict__ x,
                 const float* __restrict__ gw,
                 const float* __restrict__ gb,
                 const float* __restrict__ w1,
                 const float* __restrict__ w2)
{
    __shared__ float xs[CDIM * VP];          // [c][v]
    __shared__ float gws[NEXP * CDIM];
    __shared__ float part[4][64 * NEXP];

    const int tid = threadIdx.x;
    const int vg0 = blockIdx.x * 64;
    const int b = vg0 >> 15, s0 = vg0 & (SPATIAL - 1);
    const float* xb = x + ((size_t)b * CDIM) * SPATIAL + s0;

    for (int i = tid; i < NEXP * CDIM; i += 256) gws[i] = gw[i];

    {
        const int c16 = tid >> 4;
        const int v4  = (tid & 15) * 4;
        #pragma unroll
        for (int cc = 0; cc < CDIM; cc += 16) {
            int c = cc + c16;
            float4 xv = *(const float4*)(xb + (size_t)c * SPATIAL + v4);
            *(float4*)(xs + c * VP + v4) = xv;
        }
    }
    __syncthreads();

    // logits: thread = (v-quad 16) x (e-pair 4) x (k-quarter 4)
    {
        const int vq = tid & 15;
        const int ep = (tid >> 4) & 3;
        const int kh = tid >> 6;
        const float* g0 = gws + (2 * ep) * CDIM + kh * 32;
        const float* g1 = gws + (2 * ep + 1) * CDIM + kh * 32;
        const float* xbase = xs + kh * 32 * VP + vq * 4;
        float4 a0 = make_float4(0.f, 0.f, 0.f, 0.f);
        float4 a1 = make_float4(0.f, 0.f, 0.f, 0.f);
        #pragma unroll 8
        for (int k = 0; k < 32; k++) {
            float4 xv = *(const float4*)(xbase + (size_t)k * VP);
            float w0 = g0[k], w1v = g1[k];
            a0.x = fmaf(w0, xv.x, a0.x); a0.y = fmaf(w0, xv.y, a0.y);
            a0.z = fmaf(w0, xv.z, a0.z); a0.w = fmaf(w0, xv.w, a0.w);
            a1.x = fmaf(w1v, xv.x, a1.x); a1.y = fmaf(w1v, xv.y, a1.y);
            a1.z = fmaf(w1v, xv.z, a1.z); a1.w = fmaf(w1v, xv.w, a1.w);
        }
        float* pp = part[kh];
        pp[(vq * 4 + 0) * NEXP + 2 * ep] = a0.x;  pp[(vq * 4 + 0) * NEXP + 2 * ep + 1] = a1.x;
        pp[(vq * 4 + 1) * NEXP + 2 * ep] = a0.y;  pp[(vq * 4 + 1) * NEXP + 2 * ep + 1] = a1.y;
        pp[(vq * 4 + 2) * NEXP + 2 * ep] = a0.z;  pp[(vq * 4 + 2) * NEXP + 2 * ep + 1] = a1.z;
        pp[(vq * 4 + 3) * NEXP + 2 * ep] = a0.w;  pp[(vq * 4 + 3) * NEXP + 2 * ep + 1] = a1.w;
    }
    __syncthreads();

    if (tid < 64) {
        float l[NEXP];
        #pragma unroll
        for (int e = 0; e < NEXP; e++)
            l[e] = part[0][tid * NEXP + e] + part[1][tid * NEXP + e]
                 + part[2][tid * NEXP + e] + part[3][tid * NEXP + e] + __ldg(gb + e);
        int i0 = 0; float v0 = l[0];
        #pragma unroll
        for (int e = 1; e < NEXP; e++) { float t = l[e]; if (t > v0) { v0 = t; i0 = e; } }
        int i1 = -1; float v1 = -3.4e38f;
        #pragma unroll
        for (int e = 0; e < NEXP; e++) {
            if (e == i0) continue;
            float t = l[e]; if (t > v1) { v1 = t; i1 = e; }
        }
        float e1v = __expf(v1 - v0);
        g_route[vg0 + tid] = (unsigned short)(i0 | (i1 << 8));
        g_prob[vg0 + tid]  = 1.f / (1.f + e1v);
    }

    // emit bf16 x rows [v][c]
    {
        const int vv = tid & 63, c0 = (tid >> 6) * 32;
        uint32_t pk[16];
        #pragma unroll
        for (int j = 0; j < 16; j++) {
            int c = c0 + 2 * j;
            __nv_bfloat162 t = __float22bfloat162_rn(
                make_float2(xs[c * VP + vv], xs[(c + 1) * VP + vv]));
            pk[j] = *(uint32_t*)&t;
        }
        uint4* dst = (uint4*)(g_xbt + ((size_t)(vg0 + vv)) * CDIM + c0);
        dst[0] = *(uint4*)&pk[0];
        dst[1] = *(uint4*)&pk[4];
        dst[2] = *(uint4*)&pk[8];
        dst[3] = *(uint4*)&pk[12];
    }

    // blocks 0..63: distributed weight conversion, 16 rows each (tiny per block)
    if (blockIdx.x < 64) {
        const int row = blockIdx.x * 16 + (tid >> 4);   // 0..1023 = e*128+o
        const int k8  = (tid & 15) * 8;
        const float4* s1 = (const float4*)(w1 + (size_t)row * CDIM + k8);
        const float4* s2 = (const float4*)(w2 + (size_t)row * CDIM + k8);
        __nv_bfloat16* d1 = g_w1b + (size_t)row * CDIM + k8;
        __nv_bfloat16* d2 = g_w2b + (size_t)row * CDIM + k8;
        #pragma unroll
        for (int j = 0; j < 2; j++) {
            float4 a = s1[j];
            uint2 v;
            __nv_bfloat162 t0 = __float22bfloat162_rn(make_float2(a.x, a.y));
            __nv_bfloat162 t1 = __float22bfloat162_rn(make_float2(a.z, a.w));
            v.x = *(uint32_t*)&t0; v.y = *(uint32_t*)&t1;
            *(uint2*)(d1 + 4 * j) = v;
            float4 c = s2[j];
            t0 = __float22bfloat162_rn(make_float2(c.x, c.y));
            t1 = __float22bfloat162_rn(make_float2(c.z, c.w));
            v.x = *(uint32_t*)&t0; v.y = *(uint32_t*)&t1;
            *(uint2*)(d2 + 4 * j) = v;
        }
    }
}

// ================= K2: bf16 mma.sync expert GEMMs (fine-grained grid) =================
__global__ __launch_bounds__(256, 2)
void expert_kernel(const float* __restrict__ b1, const float* __restrict__ b2)
{
    extern __shared__ char dynsm[];
    __shared__ unsigned short lst[CHUNK];
    __shared__ float b1s[CDIM], b2s[CDIM];
    __shared__ float pvs[2][SUBV];
    __shared__ int   gvs[2][SUBV];
    __shared__ unsigned char sls[2][SUBV];
    __shared__ int   m_sh;

    const int tid = threadIdx.x;
    const int wid = tid >> 5, lane = tid & 31;
    const int chunk = blockIdx.x >> 3;
    const int e = blockIdx.x & 7;

    char* Ab  = dynsm;                 // A / H tile  [128 v][PKB]
    char* W1b = dynsm + 128 * PKB;
    char* W2b = dynsm + 256 * PKB;

    const uint32_t A_u  = smem_u32(Ab);
    const uint32_t W1_u = smem_u32(W1b);
    const uint32_t W2_u = smem_u32(W2b);

    // ---- stage W1,W2 via cp.async from pre-converted bf16 (overlaps compaction) ----
    {
        const int o = tid >> 1, half = tid & 1;
        const char* s1 = (const char*)(g_w1b + (size_t)(e * CDIM + o) * CDIM) + half * 128;
        const char* s2 = (const char*)(g_w2b + (size_t)(e * CDIM + o) * CDIM) + half * 128;
        uint32_t d1 = W1_u + (uint32_t)(o * PKB) + half * 128;
        uint32_t d2 = W2_u + (uint32_t)(o * PKB) + half * 128;
        #pragma unroll
        for (int j = 0; j < 8; j++) CP_ASYNC16(d1 + 16 * j, s1 + 16 * j);
        #pragma unroll
        for (int j = 0; j < 8; j++) CP_ASYNC16(d2 + 16 * j, s2 + 16 * j);
    }
    CP_COMMIT();

    if (wid == 0) {    // ballot compaction (sorted list)
        int cnt = 0;
        for (int it = 0; it < CHUNK / 32; it++) {
            int v = it * 32 + lane;
            unsigned rt = g_route[chunk * CHUNK + v];
            bool h1 = ((rt >> 8) == (unsigned)e);
            bool hit = ((rt & 255u) == (unsigned)e) || h1;
            unsigned msk = __ballot_sync(0xFFFFFFFFu, hit);
            if (hit) lst[cnt + __popc(msk & ((1u << lane) - 1u))] =
                         (unsigned short)(v | (h1 ? CHUNK : 0));
            cnt += __popc(msk);
        }
        if (lane == 0) m_sh = cnt;
    }
    if (tid < CDIM) {
        b1s[tid] = __ldg(b1 + e * CDIM + tid);
        b2s[tid] = __ldg(b2 + e * CDIM + tid);
    }
    __syncthreads();

    const int m = m_sh;
    if (m == 0) { CP_WAIT0(); return; }

    const int warp_m = wid & 1, warp_n = wid >> 1;
    const uint32_t a_loff = (uint32_t)((lane & 15) * PKB + (lane >> 4) * 16);
    const uint32_t b_loff = (uint32_t)(((lane & 7) + ((lane >> 4) << 3)) * PKB +
                                       ((lane >> 3) & 1) * 16);
    const int rb = warp_m * 64 + (lane >> 2);
    const int cb = warp_n * 32 + 2 * (lane & 3);

    const int gv = tid & 127, ghalf = tid >> 7;

    // ---- initial gather (buf 0) + L2 prefetch of sub-tile 1 ----
    {
        if (gv < min(SUBV, m)) {
            int en2 = lst[gv];
            int slot = (en2 & CHUNK) ? 1 : 0;
            int gvox = chunk * CHUNK + (en2 & (CHUNK - 1));
            if (ghalf == 0) {
                float p0 = g_prob[gvox];
                pvs[0][gv] = slot ? 1.f - p0 : p0;
                gvs[0][gv] = gvox; sls[0][gv] = (unsigned char)slot;
            }
            const char* src = (const char*)(g_xbt + ((size_t)gvox << 7)) + (ghalf << 7);
            uint32_t dst = A_u + (uint32_t)(gv * PKB) + (ghalf << 7);
            #pragma unroll
            for (int j = 0; j < 8; j++) CP_ASYNC16(dst + 16 * j, src + 16 * j);
        }
        int nidx = SUBV + gv;
        if (nidx < m) {
            int gvox = chunk * CHUNK + (lst[nidx] & (CHUNK - 1));
            PREF_L2((const char*)(g_xbt + ((size_t)gvox << 7)) + (ghalf << 7));
        }
        CP_COMMIT();
    }

    int buf = 0;
    for (int bse = 0; bse < m; bse += SUBV, buf ^= 1) {
        const int msub = min(SUBV, m - bse);
        int rem = msub - warp_m * 64;
        const int nmf = rem <= 0 ? 0 : (rem >= 64 ? 4 : ((rem + 15) >> 4));
        CP_WAIT0();
        __syncthreads();          // A tile + W + meta[buf] visible

        float acc[4][4][4];
        #pragma unroll
        for (int i = 0; i < 4; i++)
            #pragma unroll
            for (int j = 0; j < 4; j++)
                #pragma unroll
                for (int q = 0; q < 4; q++) acc[i][j][q] = 0.f;

        // ---- GEMM1 ----
        if (nmf > 0) {
            #pragma unroll
            for (int ks = 0; ks < 8; ks++) {
                const uint32_t kb = ks * 32;
                uint32_t af[4][4], bf[4][2];
                #pragma unroll
                for (int mf = 0; mf < 4; mf++) {
                    if (mf < nmf) {
                        uint32_t ad = A_u + (uint32_t)((warp_m * 64 + mf * 16) * PKB) + kb + a_loff;
                        LDSM_X4(af[mf][0], af[mf][1], af[mf][2], af[mf][3], ad);
                    }
                }
                #pragma unroll
                for (int np = 0; np < 2; np++) {
                    uint32_t bd = W1_u + (uint32_t)((warp_n * 32 + np * 16) * PKB) + kb + b_loff;
                    uint32_t r0, r1, r2, r3;
                    LDSM_X4(r0, r1, r2, r3, bd);
                    bf[2 * np][0] = r0; bf[2 * np][1] = r1;
                    bf[2 * np + 1][0] = r2; bf[2 * np + 1][1] = r3;
                }
                #pragma unroll
                for (int mf = 0; mf < 4; mf++)
                    if (mf < nmf)
                        #pragma unroll
                        for (int nf = 0; nf < 4; nf++)
                            MMA16816(acc[mf][nf], af[mf], bf[nf][0], bf[nf][1]);
            }
        }
        __syncthreads();          // A reads done

        // ---- epilogue 1: silu(+b1)*p -> bf16 H (reuse A tile) ----
        #pragma unroll
        for (int mf = 0; mf < 4; mf++) {
            if (mf < nmf) {
                int r0 = rb + mf * 16, r1 = r0 + 8;
                float p0 = pvs[buf][r0], p1 = pvs[buf][r1];
                #pragma unroll
                for (int nf = 0; nf < 4; nf++) {
                    int c = cb + nf * 8;
                    float bia0 = b1s[c], bia1 = b1s[c + 1];
                    float t0 = acc[mf][nf][0] + bia0, t1 = acc[mf][nf][1] + bia1;
                    float t2 = acc[mf][nf][2] + bia0, t3 = acc[mf][nf][3] + bia1;
                    float h0 = p0 * t0 * __fdividef(1.f, 1.f + __expf(-t0));
                    float h1 = p0 * t1 * __fdividef(1.f, 1.f + __expf(-t1));
                    float h2 = p1 * t2 * __fdividef(1.f, 1.f + __expf(-t2));
                    float h3 = p1 * t3 * __fdividef(1.f, 1.f + __expf(-t3));
                    __nv_bfloat162 u0 = __float22bfloat162_rn(make_float2(h0, h1));
                    __nv_bfloat162 u1 = __float22bfloat162_rn(make_float2(h2, h3));
                    *(uint32_t*)(Ab + r0 * PKB + c * 2) = *(uint32_t*)&u0;
                    *(uint32_t*)(Ab + r1 * PKB + c * 2) = *(uint32_t*)&u1;
                }
            }
        }
        __syncthreads();          // H visible

        #pragma unroll
        for (int i = 0; i < 4; i++)
            #pragma unroll
            for (int j = 0; j < 4; j++)
                #pragma unroll
                for (int q = 0; q < 4; q++) acc[i][j][q] = 0.f;

        // ---- GEMM2 ----
        if (nmf > 0) {
            #pragma unroll
            for (int ks = 0; ks < 8; ks++) {
                const uint32_t kb = ks * 32;
                uint32_t af[4][4], bf[4][2];
                #pragma unroll
                for (int mf = 0; mf < 4; mf++) {
                    if (mf < nmf) {
                        uint32_t ad = A_u + (uint32_t)((warp_m * 64 + mf * 16) * PKB) + kb + a_loff;
                        LDSM_X4(af[mf][0], af[mf][1], af[mf][2], af[mf][3], ad);
                    }
                }
                #pragma unroll
                for (int np = 0; np < 2; np++) {
                    uint32_t bd = W2_u + (uint32_t)((warp_n * 32 + np * 16) * PKB) + kb + b_loff;
                    uint32_t r0, r1, r2, r3;
                    LDSM_X4(r0, r1, r2, r3, bd);
                    bf[2 * np][0] = r0; bf[2 * np][1] = r1;
                    bf[2 * np + 1][0] = r2; bf[2 * np + 1][1] = r3;
                }
                #pragma unroll
                for (int mf = 0; mf < 4; mf++)
                    if (mf < nmf)
                        #pragma unroll
                        for (int nf = 0; nf < 4; nf++)
                            MMA16816(acc[mf][nf], af[mf], bf[nf][0], bf[nf][1]);
            }
        }
        __syncthreads();          // H reads done -> safe to overwrite A

        // ---- issue next sub-tile gather (overlaps epilogue 2) + L2 prefetch ----
        if (bse + SUBV < m) {
            int msn = min(SUBV, m - (bse + SUBV));
            if (gv < msn) {
                int en2 = lst[bse + SUBV + gv];
                int slot = (en2 & CHUNK) ? 1 : 0;
                int gvox = chunk * CHUNK + (en2 & (CHUNK - 1));
                if (ghalf == 0) {
                    float p0 = g_prob[gvox];
                    pvs[buf ^ 1][gv] = slot ? 1.f - p0 : p0;
                    gvs[buf ^ 1][gv] = gvox; sls[buf ^ 1][gv] = (unsigned char)slot;
                }
                const char* src = (const char*)(g_xbt + ((size_t)gvox << 7)) + (ghalf << 7);
                uint32_t dst = A_u + (uint32_t)(gv * PKB) + (ghalf << 7);
                #pragma unroll
                for (int j = 0; j < 8; j++) CP_ASYNC16(dst + 16 * j, src + 16 * j);
            }
            int nidx = bse + 2 * SUBV + gv;
            if (nidx < m) {
                int gvox = chunk * CHUNK + (lst[nidx] & (CHUNK - 1));
                PREF_L2((const char*)(g_xbt + ((size_t)gvox << 7)) + (ghalf << 7));
            }
        }
        CP_COMMIT();

        // ---- epilogue 2: + p*b2 -> bf16x2 stores ----
        #pragma unroll
        for (int mf = 0; mf < 4; mf++) {
            if (mf < nmf) {
                int r0 = rb + mf * 16;
                #pragma unroll
                for (int half = 0; half < 2; half++) {
                    int r = r0 + half * 8;
                    if (r < msub) {
                        float p = pvs[buf][r];
                        __nv_bfloat16* yb = (sls[buf][r] ? g_y1h : g_y0h) +
                                            ((size_t)gvs[buf][r] << 7);
                        #pragma unroll
                        for (int nf = 0; nf < 4; nf++) {
                            int c = cb + nf * 8;
                            float o0 = acc[mf][nf][2 * half]     + p * b2s[c];
                            float o1 = acc[mf][nf][2 * half + 1] + p * b2s[c + 1];
                            __nv_bfloat162 t = __float22bfloat162_rn(make_float2(o0, o1));
                            *(uint32_t*)(yb + c) = *(uint32_t*)&t;
                        }
                    }
                }
            }
        }
    }
    CP_WAIT0();   // drain any outstanding cp.async before exit
}

// ================= K3: combine out = x + y0 + y1 (transpose) =================
__global__ __launch_bounds__(256)
void combine_kernel(const float* __restrict__ x, float* __restrict__ out)
{
    __shared__ float ts[CDIM * CP];
    const int tid = threadIdx.x;
    const int vg0 = blockIdx.x * 64;
    const int b = vg0 >> 15, s0 = vg0 & (SPATIAL - 1);

    const uint4* y04 = (const uint4*)(g_y0h + ((size_t)vg0 << 7));
    const uint4* y14 = (const uint4*)(g_y1h + ((size_t)vg0 << 7));
    #pragma unroll
    for (int j = 0; j < 4; j++) {
        int u = j * 256 + tid;
        int v = u >> 4;
        int c0 = (u & 15) * 8;
        uint4 a = y04[u], c = y14[u];
        const __nv_bfloat162* pa = (const __nv_bfloat162*)&a;
        const __nv_bfloat162* pc = (const __nv_bfloat162*)&c;
        #pragma unroll
        for (int q = 0; q < 4; q++) {
            float2 fa = __bfloat1622float2(pa[q]);
            float2 fc = __bfloat1622float2(pc[q]);
            ts[(c0 + 2 * q) * CP + v]     = fa.x + fc.x;
            ts[(c0 + 2 * q + 1) * CP + v] = fa.y + fc.y;
        }
    }
    __syncthreads();

    const int c_sub = tid >> 6, iv = tid & 63;
    const float* xb = x   + ((size_t)b * CDIM) * SPATIAL + s0;
    float*       ob = out + ((size_t)b * CDIM) * SPATIAL + s0;
    #pragma unroll
    for (int cc = 0; cc < CDIM; cc += 4) {
        int c = cc + c_sub;
        ob[(size_t)c * SPATIAL + iv] = ts[c * CP + iv] + xb[(size_t)c * SPATIAL + iv];
    }
}

// ================= launch =================
extern "C" void kernel_launch(void* const* d_in, const int* in_sizes, int n_in,
                              void* d_out, int out_size) {
    const float* x   = (const float*)d_in[0];
    const float* gwp = (const float*)d_in[1];
    const float* gbp = (const float*)d_in[2];
    const float* w1p = (const float*)d_in[3];
    const float* b1p = (const float*)d_in[4];
    const float* w2p = (const float*)d_in[5];
    const float* b2p = (const float*)d_in[6];
    float* outp = (float*)d_out;

    static int smem_set = 0;
    const int dyn_smem = 3 * 128 * PKB;   // 104448 B
    if (!smem_set) {
        cudaFuncSetAttribute(expert_kernel,
                             cudaFuncAttributeMaxDynamicSharedMemorySize, dyn_smem);
        smem_set = 1;
    }

    gate_kernel<<<NVOX / 64, 256>>>(x, gwp, gbp, w1p, w2p);
    expert_kernel<<<NCHUNK * NEXP, 256, dyn_smem>>>(b1p, b2p);
    combine_kernel<<<NVOX / 64, 256>>>(x, outp);
}

// round 12
// speedup vs baseline: 1.0525x; 1.0525x over previous
#include <cuda_runtime.h>
#include <cuda_bf16.h>
#include <cstdint>

#define CDIM    128
#define NEXP    8
#define SPATIAL 32768
#define NVOX    65536
#define CHUNK   1024
#define NCHUNK  (NVOX / CHUNK)   // 64
#define SUBV    128
#define PKB     272           // expert smem tile row pitch (bytes)
#define VP      68            // gate smem [c][v] pitch (floats)
#define CP      65            // combine smem [c][v] pitch (floats)

// ---------------- device scratch ----------------
__device__ __nv_bfloat16 g_xbt[(size_t)NVOX * CDIM];   // x, bf16, [v][c]
__device__ __nv_bfloat16 g_y0h[(size_t)NVOX * CDIM];   // slot-0 y, bf16, [v][c]
__device__ __nv_bfloat16 g_y1h[(size_t)NVOX * CDIM];   // slot-1 y, bf16, [v][c]
__device__ __nv_bfloat16 g_w1b[NEXP * CDIM * CDIM];    // W1 bf16, [e][o][k]
__device__ __nv_bfloat16 g_w2b[NEXP * CDIM * CDIM];    // W2 bf16, [e][o][k]
__device__ unsigned short g_route[NVOX];
__device__ float          g_prob[NVOX];

__device__ __forceinline__ uint32_t smem_u32(const void* p) {
    uint32_t a;
    asm("{ .reg .u64 t; cvta.to.shared.u64 t, %1; cvt.u32.u64 %0, t; }" : "=r"(a) : "l"(p));
    return a;
}

#define LDSM_X4(r0, r1, r2, r3, addr) \
    asm volatile("ldmatrix.sync.aligned.m8n8.x4.shared.b16 {%0,%1,%2,%3}, [%4];" \
        : "=r"(r0), "=r"(r1), "=r"(r2), "=r"(r3) : "r"(addr))

#define MMA16816(c, a, b0v, b1v) \
    asm volatile("mma.sync.aligned.m16n8k16.row.col.f32.bf16.bf16.f32 " \
        "{%0,%1,%2,%3}, {%4,%5,%6,%7}, {%8,%9}, {%0,%1,%2,%3};" \
        : "+f"((c)[0]), "+f"((c)[1]), "+f"((c)[2]), "+f"((c)[3]) \
        : "r"((a)[0]), "r"((a)[1]), "r"((a)[2]), "r"((a)[3]), "r"(b0v), "r"(b1v))

#define CP_ASYNC16(dst, src) \
    asm volatile("cp.async.ca.shared.global [%0], [%1], 16;" :: "r"(dst), "l"(src))
#define CP_COMMIT() asm volatile("cp.async.commit_group;")
#define CP_WAIT0()  asm volatile("cp.async.wait_group 0;" ::: "memory")
#define PREF_L2(p)  asm volatile("prefetch.global.L2 [%0];" :: "l"(p))

// ================= K1: gate + bf16 xT emission + distributed weight conversion =================
__global__ __launch_bounds__(256)
void gate_kernel(const float* __restrict__ x,
                 const float* __restrict__ gw,
                 const float* __restrict__ gb,
                 const float* __restrict__ w1,
                 const float* __restrict__ w2)
{
    __shared__ float xs[CDIM * VP];          // [c][v]
    __shared__ float gws[NEXP * CDIM];
    __shared__ float part[4][64 * NEXP];

    const int tid = threadIdx.x;
    const int vg0 = blockIdx.x * 64;
    const int b = vg0 >> 15, s0 = vg0 & (SPATIAL - 1);
    const float* xb = x + ((size_t)b * CDIM) * SPATIAL + s0;

    for (int i = tid; i < NEXP * CDIM; i += 256) gws[i] = gw[i];

    {
        const int c16 = tid >> 4;
        const int v4  = (tid & 15) * 4;
        #pragma unroll
        for (int cc = 0; cc < CDIM; cc += 16) {
            int c = cc + c16;
            float4 xv = *(const float4*)(xb + (size_t)c * SPATIAL + v4);
            *(float4*)(xs + c * VP + v4) = xv;
        }
    }
    __syncthreads();

    // logits: thread = (v-quad 16) x (e-pair 4) x (k-quarter 4)
    {
        const int vq = tid & 15;
        const int ep = (tid >> 4) & 3;
        const int kh = tid >> 6;
        const float* g0 = gws + (2 * ep) * CDIM + kh * 32;
        const float* g1 = gws + (2 * ep + 1) * CDIM + kh * 32;
        const float* xbase = xs + kh * 32 * VP + vq * 4;
        float4 a0 = make_float4(0.f, 0.f, 0.f, 0.f);
        float4 a1 = make_float4(0.f, 0.f, 0.f, 0.f);
        #pragma unroll 8
        for (int k = 0; k < 32; k++) {
            float4 xv = *(const float4*)(xbase + (size_t)k * VP);
            float w0 = g0[k], w1v = g1[k];
            a0.x = fmaf(w0, xv.x, a0.x); a0.y = fmaf(w0, xv.y, a0.y);
            a0.z = fmaf(w0, xv.z, a0.z); a0.w = fmaf(w0, xv.w, a0.w);
            a1.x = fmaf(w1v, xv.x, a1.x); a1.y = fmaf(w1v, xv.y, a1.y);
            a1.z = fmaf(w1v, xv.z, a1.z); a1.w = fmaf(w1v, xv.w, a1.w);
        }
        float* pp = part[kh];
        pp[(vq * 4 + 0) * NEXP + 2 * ep] = a0.x;  pp[(vq * 4 + 0) * NEXP + 2 * ep + 1] = a1.x;
        pp[(vq * 4 + 1) * NEXP + 2 * ep] = a0.y;  pp[(vq * 4 + 1) * NEXP + 2 * ep + 1] = a1.y;
        pp[(vq * 4 + 2) * NEXP + 2 * ep] = a0.z;  pp[(vq * 4 + 2) * NEXP + 2 * ep + 1] = a1.z;
        pp[(vq * 4 + 3) * NEXP + 2 * ep] = a0.w;  pp[(vq * 4 + 3) * NEXP + 2 * ep + 1] = a1.w;
    }
    __syncthreads();

    if (tid < 64) {
        float l[NEXP];
        #pragma unroll
        for (int e = 0; e < NEXP; e++)
            l[e] = part[0][tid * NEXP + e] + part[1][tid * NEXP + e]
                 + part[2][tid * NEXP + e] + part[3][tid * NEXP + e] + __ldg(gb + e);
        int i0 = 0; float v0 = l[0];
        #pragma unroll
        for (int e = 1; e < NEXP; e++) { float t = l[e]; if (t > v0) { v0 = t; i0 = e; } }
        int i1 = -1; float v1 = -3.4e38f;
        #pragma unroll
        for (int e = 0; e < NEXP; e++) {
            if (e == i0) continue;
            float t = l[e]; if (t > v1) { v1 = t; i1 = e; }
        }
        float e1v = __expf(v1 - v0);
        g_route[vg0 + tid] = (unsigned short)(i0 | (i1 << 8));
        g_prob[vg0 + tid]  = 1.f / (1.f + e1v);
    }

    // emit bf16 x rows [v][c]
    {
        const int vv = tid & 63, c0 = (tid >> 6) * 32;
        uint32_t pk[16];
        #pragma unroll
        for (int j = 0; j < 16; j++) {
            int c = c0 + 2 * j;
            __nv_bfloat162 t = __float22bfloat162_rn(
                make_float2(xs[c * VP + vv], xs[(c + 1) * VP + vv]));
            pk[j] = *(uint32_t*)&t;
        }
        uint4* dst = (uint4*)(g_xbt + ((size_t)(vg0 + vv)) * CDIM + c0);
        dst[0] = *(uint4*)&pk[0];
        dst[1] = *(uint4*)&pk[4];
        dst[2] = *(uint4*)&pk[8];
        dst[3] = *(uint4*)&pk[12];
    }

    // blocks 0..63: distributed weight conversion, 16 rows each (tiny per block)
    if (blockIdx.x < 64) {
        const int row = blockIdx.x * 16 + (tid >> 4);   // 0..1023 = e*128+o
        const int k8  = (tid & 15) * 8;
        const float4* s1 = (const float4*)(w1 + (size_t)row * CDIM + k8);
        const float4* s2 = (const float4*)(w2 + (size_t)row * CDIM + k8);
        __nv_bfloat16* d1 = g_w1b + (size_t)row * CDIM + k8;
        __nv_bfloat16* d2 = g_w2b + (size_t)row * CDIM + k8;
        #pragma unroll
        for (int j = 0; j < 2; j++) {
            float4 a = s1[j];
            uint2 v;
            __nv_bfloat162 t0 = __float22bfloat162_rn(make_float2(a.x, a.y));
            __nv_bfloat162 t1 = __float22bfloat162_rn(make_float2(a.z, a.w));
            v.x = *(uint32_t*)&t0; v.y = *(uint32_t*)&t1;
            *(uint2*)(d1 + 4 * j) = v;
            float4 c = s2[j];
            t0 = __float22bfloat162_rn(make_float2(c.x, c.y));
            t1 = __float22bfloat162_rn(make_float2(c.z, c.w));
            v.x = *(uint32_t*)&t0; v.y = *(uint32_t*)&t1;
            *(uint2*)(d2 + 4 * j) = v;
        }
    }
}

// ================= K2: bf16 mma.sync expert GEMMs (CHUNK=1024, pipelined gather) =================
__global__ __launch_bounds__(256, 2)
void expert_kernel(const float* __restrict__ b1, const float* __restrict__ b2)
{
    extern __shared__ char dynsm[];
    __shared__ unsigned short lst[CHUNK];
    __shared__ float b1s[CDIM], b2s[CDIM];
    __shared__ float pvs[2][SUBV];
    __shared__ int   gvs[2][SUBV];
    __shared__ unsigned char sls[2][SUBV];
    __shared__ int   m_sh;

    const int tid = threadIdx.x;
    const int wid = tid >> 5, lane = tid & 31;
    const int chunk = blockIdx.x >> 3;
    const int e = blockIdx.x & 7;

    char* Ab  = dynsm;                 // A / H tile  [128 v][PKB]
    char* W1b = dynsm + 128 * PKB;
    char* W2b = dynsm + 256 * PKB;

    const uint32_t A_u  = smem_u32(Ab);
    const uint32_t W1_u = smem_u32(W1b);
    const uint32_t W2_u = smem_u32(W2b);

    // ---- stage W1,W2 via cp.async from pre-converted bf16 (overlaps compaction) ----
    {
        const int o = tid >> 1, half = tid & 1;
        const char* s1 = (const char*)(g_w1b + (size_t)(e * CDIM + o) * CDIM) + half * 128;
        const char* s2 = (const char*)(g_w2b + (size_t)(e * CDIM + o) * CDIM) + half * 128;
        uint32_t d1 = W1_u + (uint32_t)(o * PKB) + half * 128;
        uint32_t d2 = W2_u + (uint32_t)(o * PKB) + half * 128;
        #pragma unroll
        for (int j = 0; j < 8; j++) CP_ASYNC16(d1 + 16 * j, s1 + 16 * j);
        #pragma unroll
        for (int j = 0; j < 8; j++) CP_ASYNC16(d2 + 16 * j, s2 + 16 * j);
    }
    CP_COMMIT();

    if (wid == 0) {    // ballot compaction (sorted list)
        int cnt = 0;
        for (int it = 0; it < CHUNK / 32; it++) {
            int v = it * 32 + lane;
            unsigned rt = g_route[chunk * CHUNK + v];
            bool h1 = ((rt >> 8) == (unsigned)e);
            bool hit = ((rt & 255u) == (unsigned)e) || h1;
            unsigned msk = __ballot_sync(0xFFFFFFFFu, hit);
            if (hit) lst[cnt + __popc(msk & ((1u << lane) - 1u))] =
                         (unsigned short)(v | (h1 ? CHUNK : 0));
            cnt += __popc(msk);
        }
        if (lane == 0) m_sh = cnt;
    }
    if (tid < CDIM) {
        b1s[tid] = __ldg(b1 + e * CDIM + tid);
        b2s[tid] = __ldg(b2 + e * CDIM + tid);
    }
    __syncthreads();

    const int m = m_sh;
    if (m == 0) { CP_WAIT0(); return; }

    const int warp_m = wid & 1, warp_n = wid >> 1;
    const uint32_t a_loff = (uint32_t)((lane & 15) * PKB + (lane >> 4) * 16);
    const uint32_t b_loff = (uint32_t)(((lane & 7) + ((lane >> 4) << 3)) * PKB +
                                       ((lane >> 3) & 1) * 16);
    const int rb = warp_m * 64 + (lane >> 2);
    const int cb = warp_n * 32 + 2 * (lane & 3);

    const int gv = tid & 127, ghalf = tid >> 7;

    // ---- initial gather (buf 0) + L2 prefetch of sub-tile 1 ----
    {
        if (gv < min(SUBV, m)) {
            int en2 = lst[gv];
            int slot = (en2 & CHUNK) ? 1 : 0;
            int gvox = chunk * CHUNK + (en2 & (CHUNK - 1));
            if (ghalf == 0) {
                float p0 = g_prob[gvox];
                pvs[0][gv] = slot ? 1.f - p0 : p0;
                gvs[0][gv] = gvox; sls[0][gv] = (unsigned char)slot;
            }
            const char* src = (const char*)(g_xbt + ((size_t)gvox << 7)) + (ghalf << 7);
            uint32_t dst = A_u + (uint32_t)(gv * PKB) + (ghalf << 7);
            #pragma unroll
            for (int j = 0; j < 8; j++) CP_ASYNC16(dst + 16 * j, src + 16 * j);
        }
        int nidx = SUBV + gv;
        if (nidx < m) {
            int gvox = chunk * CHUNK + (lst[nidx] & (CHUNK - 1));
            PREF_L2((const char*)(g_xbt + ((size_t)gvox << 7)) + (ghalf << 7));
        }
        CP_COMMIT();
    }

    int buf = 0;
    for (int bse = 0; bse < m; bse += SUBV, buf ^= 1) {
        const int msub = min(SUBV, m - bse);
        int rem = msub - warp_m * 64;
        const int nmf = rem <= 0 ? 0 : (rem >= 64 ? 4 : ((rem + 15) >> 4));
        CP_WAIT0();
        __syncthreads();          // A tile + W + meta[buf] visible

        float acc[4][4][4];
        #pragma unroll
        for (int i = 0; i < 4; i++)
            #pragma unroll
            for (int j = 0; j < 4; j++)
                #pragma unroll
                for (int q = 0; q < 4; q++) acc[i][j][q] = 0.f;

        // ---- GEMM1 ----
        if (nmf > 0) {
            #pragma unroll
            for (int ks = 0; ks < 8; ks++) {
                const uint32_t kb = ks * 32;
                uint32_t af[4][4], bf[4][2];
                #pragma unroll
                for (int mf = 0; mf < 4; mf++) {
                    if (mf < nmf) {
                        uint32_t ad = A_u + (uint32_t)((warp_m * 64 + mf * 16) * PKB) + kb + a_loff;
                        LDSM_X4(af[mf][0], af[mf][1], af[mf][2], af[mf][3], ad);
                    }
                }
                #pragma unroll
                for (int np = 0; np < 2; np++) {
                    uint32_t bd = W1_u + (uint32_t)((warp_n * 32 + np * 16) * PKB) + kb + b_loff;
                    uint32_t r0, r1, r2, r3;
                    LDSM_X4(r0, r1, r2, r3, bd);
                    bf[2 * np][0] = r0; bf[2 * np][1] = r1;
                    bf[2 * np + 1][0] = r2; bf[2 * np + 1][1] = r3;
                }
                #pragma unroll
                for (int mf = 0; mf < 4; mf++)
                    if (mf < nmf)
                        #pragma unroll
                        for (int nf = 0; nf < 4; nf++)
                            MMA16816(acc[mf][nf], af[mf], bf[nf][0], bf[nf][1]);
            }
        }
        __syncthreads();          // A reads done

        // ---- epilogue 1: silu(+b1)*p -> bf16 H (reuse A tile) ----
        #pragma unroll
        for (int mf = 0; mf < 4; mf++) {
            if (mf < nmf) {
                int r0 = rb + mf * 16, r1 = r0 + 8;
                float p0 = pvs[buf][r0], p1 = pvs[buf][r1];
                #pragma unroll
                for (int nf = 0; nf < 4; nf++) {
                    int c = cb + nf * 8;
                    float bia0 = b1s[c], bia1 = b1s[c + 1];
                    float t0 = acc[mf][nf][0] + bia0, t1 = acc[mf][nf][1] + bia1;
                    float t2 = acc[mf][nf][2] + bia0, t3 = acc[mf][nf][3] + bia1;
                    float h0 = p0 * t0 * __fdividef(1.f, 1.f + __expf(-t0));
                    float h1 = p0 * t1 * __fdividef(1.f, 1.f + __expf(-t1));
                    float h2 = p1 * t2 * __fdividef(1.f, 1.f + __expf(-t2));
                    float h3 = p1 * t3 * __fdividef(1.f, 1.f + __expf(-t3));
                    __nv_bfloat162 u0 = __float22bfloat162_rn(make_float2(h0, h1));
                    __nv_bfloat162 u1 = __float22bfloat162_rn(make_float2(h2, h3));
                    *(uint32_t*)(Ab + r0 * PKB + c * 2) = *(uint32_t*)&u0;
                    *(uint32_t*)(Ab + r1 * PKB + c * 2) = *(uint32_t*)&u1;
                }
            }
        }
        __syncthreads();          // H visible

        #pragma unroll
        for (int i = 0; i < 4; i++)
            #pragma unroll
            for (int j = 0; j < 4; j++)
                #pragma unroll
                for (int q = 0; q < 4; q++) acc[i][j][q] = 0.f;

        // ---- GEMM2 ----
        if (nmf > 0) {
            #pragma unroll
            for (int ks = 0; ks < 8; ks++) {
                const uint32_t kb = ks * 32;
                uint32_t af[4][4], bf[4][2];
                #pragma unroll
                for (int mf = 0; mf < 4; mf++) {
                    if (mf < nmf) {
                        uint32_t ad = A_u + (uint32_t)((warp_m * 64 + mf * 16) * PKB) + kb + a_loff;
                        LDSM_X4(af[mf][0], af[mf][1], af[mf][2], af[mf][3], ad);
                    }
                }
                #pragma unroll
                for (int np = 0; np < 2; np++) {
                    uint32_t bd = W2_u + (uint32_t)((warp_n * 32 + np * 16) * PKB) + kb + b_loff;
                    uint32_t r0, r1, r2, r3;
                    LDSM_X4(r0, r1, r2, r3, bd);
                    bf[2 * np][0] = r0; bf[2 * np][1] = r1;
                    bf[2 * np + 1][0] = r2; bf[2 * np + 1][1] = r3;
                }
                #pragma unroll
                for (int mf = 0; mf < 4; mf++)
                    if (mf < nmf)
                        #pragma unroll
                        for (int nf = 0; nf < 4; nf++)
                            MMA16816(acc[mf][nf], af[mf], bf[nf][0], bf[nf][1]);
            }
        }
        __syncthreads();          // H reads done -> safe to overwrite A

        // ---- issue next sub-tile gather (overlaps epilogue 2) + L2 prefetch ----
        if (bse + SUBV < m) {
            int msn = min(SUBV, m - (bse + SUBV));
            if (gv < msn) {
                int en2 = lst[bse + SUBV + gv];
                int slot = (en2 & CHUNK) ? 1 : 0;
                int gvox = chunk * CHUNK + (en2 & (CHUNK - 1));
                if (ghalf == 0) {
                    float p0 = g_prob[gvox];
                    pvs[buf ^ 1][gv] = slot ? 1.f - p0 : p0;
                    gvs[buf ^ 1][gv] = gvox; sls[buf ^ 1][gv] = (unsigned char)slot;
                }
                const char* src = (const char*)(g_xbt + ((size_t)gvox << 7)) + (ghalf << 7);
                uint32_t dst = A_u + (uint32_t)(gv * PKB) + (ghalf << 7);
                #pragma unroll
                for (int j = 0; j < 8; j++) CP_ASYNC16(dst + 16 * j, src + 16 * j);
            }
            int nidx = bse + 2 * SUBV + gv;
            if (nidx < m) {
                int gvox = chunk * CHUNK + (lst[nidx] & (CHUNK - 1));
                PREF_L2((const char*)(g_xbt + ((size_t)gvox << 7)) + (ghalf << 7));
            }
        }
        CP_COMMIT();

        // ---- epilogue 2: + p*b2 -> bf16x2 stores ----
        #pragma unroll
        for (int mf = 0; mf < 4; mf++) {
            if (mf < nmf) {
                int r0 = rb + mf * 16;
                #pragma unroll
                for (int half = 0; half < 2; half++) {
                    int r = r0 + half * 8;
                    if (r < msub) {
                        float p = pvs[buf][r];
                        __nv_bfloat16* yb = (sls[buf][r] ? g_y1h : g_y0h) +
                                            ((size_t)gvs[buf][r] << 7);
                        #pragma unroll
                        for (int nf = 0; nf < 4; nf++) {
                            int c = cb + nf * 8;
                            float o0 = acc[mf][nf][2 * half]     + p * b2s[c];
                            float o1 = acc[mf][nf][2 * half + 1] + p * b2s[c + 1];
                            __nv_bfloat162 t = __float22bfloat162_rn(make_float2(o0, o1));
                            *(uint32_t*)(yb + c) = *(uint32_t*)&t;
                        }
                    }
                }
            }
        }
    }
    CP_WAIT0();   // drain any outstanding cp.async before exit
}

// ================= K3: combine out = x + y0 + y1 (transpose) =================
__global__ __launch_bounds__(256)
void combine_kernel(const float* __restrict__ x, float* __restrict__ out)
{
    __shared__ float ts[CDIM * CP];
    const int tid = threadIdx.x;
    const int vg0 = blockIdx.x * 64;
    const int b = vg0 >> 15, s0 = vg0 & (SPATIAL - 1);

    const uint4* y04 = (const uint4*)(g_y0h + ((size_t)vg0 << 7));
    const uint4* y14 = (const uint4*)(g_y1h + ((size_t)vg0 << 7));
    #pragma unroll
    for (int j = 0; j < 4; j++) {
        int u = j * 256 + tid;
        int v = u >> 4;
        int c0 = (u & 15) * 8;
        uint4 a = y04[u], c = y14[u];
        const __nv_bfloat162* pa = (const __nv_bfloat162*)&a;
        const __nv_bfloat162* pc = (const __nv_bfloat162*)&c;
        #pragma unroll
        for (int q = 0; q < 4; q++) {
            float2 fa = __bfloat1622float2(pa[q]);
            float2 fc = __bfloat1622float2(pc[q]);
            ts[(c0 + 2 * q) * CP + v]     = fa.x + fc.x;
            ts[(c0 + 2 * q + 1) * CP + v] = fa.y + fc.y;
        }
    }
    __syncthreads();

    const int c_sub = tid >> 6, iv = tid & 63;
    const float* xb = x   + ((size_t)b * CDIM) * SPATIAL + s0;
    float*       ob = out + ((size_t)b * CDIM) * SPATIAL + s0;
    #pragma unroll
    for (int cc = 0; cc < CDIM; cc += 4) {
        int c = cc + c_sub;
        ob[(size_t)c * SPATIAL + iv] = ts[c * CP + iv] + xb[(size_t)c * SPATIAL + iv];
    }
}

// ================= launch =================
extern "C" void kernel_launch(void* const* d_in, const int* in_sizes, int n_in,
                              void* d_out, int out_size) {
    const float* x   = (const float*)d_in[0];
    const float* gwp = (const float*)d_in[1];
    const float* gbp = (const float*)d_in[2];
    const float* w1p = (const float*)d_in[3];
    const float* b1p = (const float*)d_in[4];
    const float* w2p = (const float*)d_in[5];
    const float* b2p = (const float*)d_in[6];
    float* outp = (float*)d_out;

    static int smem_set = 0;
    const int dyn_smem = 3 * 128 * PKB;   // 104448 B
    if (!smem_set) {
        cudaFuncSetAttribute(expert_kernel,
                             cudaFuncAttributeMaxDynamicSharedMemorySize, dyn_smem);
        smem_set = 1;
    }

    gate_kernel<<<NVOX / 64, 256>>>(x, gwp, gbp, w1p, w2p);
    expert_kernel<<<NCHUNK * NEXP, 256, dyn_smem>>>(b1p, b2p);
    combine_kernel<<<NVOX / 64, 256>>>(x, outp);
}